// round 2
// baseline (speedup 1.0000x reference)
#include <cuda_runtime.h>

#define N_NODES 10000
#define N_EDGES 640000
#define D 128
#define BN_EPS 1e-5f

// ---------------- scratch (device globals: no allocations allowed) ----------
__device__ int   g_counts [N_NODES];
__device__ int   g_cursor [N_NODES];
__device__ int   g_offsets[N_NODES + 1];
__device__ int   g_sorted [N_EDGES];
__device__ float g_h0 [N_NODES * D];        // GIN combine output        [10000,128]
__device__ float g_t1 [N_NODES * 2 * D];    // after GEMM1               [10000,256]
__device__ float g_t2 [N_NODES * D];        // after GEMM2               [10000,128]
__device__ float g_bnsum[1024];             // [0:512) stage1 sum/sumsq, [512:1024) stage2

// ---------------- zero scratch ----------------------------------------------
__global__ void zero_kernel() {
    int i = blockIdx.x * blockDim.x + threadIdx.x;
    if (i < N_NODES) { g_counts[i] = 0; g_cursor[i] = 0; }
    if (i < 1024)    { g_bnsum[i] = 0.0f; }
}

// ---------------- degree histogram ------------------------------------------
__global__ void hist_kernel(const int* __restrict__ dst) {
    int e = blockIdx.x * blockDim.x + threadIdx.x;
    if (e < N_EDGES) atomicAdd(&g_counts[dst[e]], 1);
}

// ---------------- single-block exclusive scan (10000 elements) --------------
__global__ void scan_kernel() {
    __shared__ int s[1024];
    const int CH = (N_NODES + 1023) / 1024;   // 10
    int tid = threadIdx.x;
    int base = tid * CH;
    int sum = 0;
    for (int i = 0; i < CH; i++) {
        int idx = base + i;
        if (idx < N_NODES) sum += g_counts[idx];
    }
    s[tid] = sum;
    __syncthreads();
    // Hillis-Steele inclusive scan
    for (int off = 1; off < 1024; off <<= 1) {
        int v = (tid >= off) ? s[tid - off] : 0;
        __syncthreads();
        s[tid] += v;
        __syncthreads();
    }
    int run = s[tid] - sum;   // exclusive prefix for this thread's chunk
    for (int i = 0; i < CH; i++) {
        int idx = base + i;
        if (idx < N_NODES) {
            g_offsets[idx] = run;
            run += g_counts[idx];
        }
    }
    if (tid == 1023) g_offsets[N_NODES] = s[1023];
}

// ---------------- scatter edge indices into CSR ------------------------------
__global__ void scatter_kernel(const int* __restrict__ dst) {
    int e = blockIdx.x * blockDim.x + threadIdx.x;
    if (e < N_EDGES) {
        int d = dst[e];
        int p = g_offsets[d] + atomicAdd(&g_cursor[d], 1);
        g_sorted[p] = e;
    }
}

// ---------------- per-node aggregation (one warp per node) -------------------
__global__ void aggregate_kernel(const float* __restrict__ nf,
                                 const float* __restrict__ ef,
                                 const int*   __restrict__ src,
                                 const float* __restrict__ eps) {
    int gw   = (blockIdx.x * blockDim.x + threadIdx.x) >> 5;
    int lane = threadIdx.x & 31;
    if (gw >= N_NODES) return;
    int beg = g_offsets[gw], end = g_offsets[gw + 1];

    float4 acc0 = make_float4(0.f, 0.f, 0.f, 0.f);
    float4 acc1 = make_float4(0.f, 0.f, 0.f, 0.f);
    int i = beg;
    for (; i + 2 <= end; i += 2) {
        int e0 = g_sorted[i], e1 = g_sorted[i + 1];
        int s0 = src[e0],     s1 = src[e1];
        float4 a0 = ((const float4*)(nf + (size_t)s0 * D))[lane];
        float4 b0 = ((const float4*)(ef + (size_t)e0 * D))[lane];
        float4 a1 = ((const float4*)(nf + (size_t)s1 * D))[lane];
        float4 b1 = ((const float4*)(ef + (size_t)e1 * D))[lane];
        acc0.x += a0.x + b0.x; acc0.y += a0.y + b0.y;
        acc0.z += a0.z + b0.z; acc0.w += a0.w + b0.w;
        acc1.x += a1.x + b1.x; acc1.y += a1.y + b1.y;
        acc1.z += a1.z + b1.z; acc1.w += a1.w + b1.w;
    }
    if (i < end) {
        int e0 = g_sorted[i];
        int s0 = src[e0];
        float4 a0 = ((const float4*)(nf + (size_t)s0 * D))[lane];
        float4 b0 = ((const float4*)(ef + (size_t)e0 * D))[lane];
        acc0.x += a0.x + b0.x; acc0.y += a0.y + b0.y;
        acc0.z += a0.z + b0.z; acc0.w += a0.w + b0.w;
    }
    float cnt = (float)(end - beg);
    float inv = 1.0f / fmaxf(cnt, 1.0f);
    float sc  = 1.0f + eps[0];
    float4 m  = ((const float4*)(nf + (size_t)gw * D))[lane];
    float4 o;
    o.x = sc * m.x + (acc0.x + acc1.x) * inv;
    o.y = sc * m.y + (acc0.y + acc1.y) * inv;
    o.z = sc * m.z + (acc0.z + acc1.z) * inv;
    o.w = sc * m.w + (acc0.w + acc1.w) * inv;
    ((float4*)(g_h0 + (size_t)gw * D))[lane] = o;
}

// ---------------- SGEMM: C[M,N] = A[M,K] @ B[K,N] + bias ---------------------
#define GBM 128
#define GBN 64
#define GBK 16
#define GTM 8
#define GTN 4

__global__ __launch_bounds__(256) void sgemm_bias(const float* __restrict__ A,
                                                  const float* __restrict__ B,
                                                  const float* __restrict__ bias,
                                                  float* __restrict__ C,
                                                  int M, int N, int K) {
    __shared__ float As[GBK * GBM];
    __shared__ float Bs[GBK * GBN];
    int tid = threadIdx.x;
    int tx = tid & 15;      // N direction (16)
    int ty = tid >> 4;      // M direction (16)
    int bm = blockIdx.y * GBM;
    int bn = blockIdx.x * GBN;

    float acc[GTM][GTN];
    #pragma unroll
    for (int a = 0; a < GTM; a++)
        #pragma unroll
        for (int b = 0; b < GTN; b++) acc[a][b] = 0.f;

    for (int k0 = 0; k0 < K; k0 += GBK) {
        // Load A tile (128x16 = 512 float4), 2 per thread; store transposed.
        #pragma unroll
        for (int t = 0; t < 2; t++) {
            int j   = tid + t * 256;
            int row = j >> 2;
            int kc  = (j & 3) * 4;
            int gr  = bm + row;
            float4 a = make_float4(0.f, 0.f, 0.f, 0.f);
            if (gr < M) a = *(const float4*)(A + (size_t)gr * K + k0 + kc);
            As[(kc + 0) * GBM + row] = a.x;
            As[(kc + 1) * GBM + row] = a.y;
            As[(kc + 2) * GBM + row] = a.z;
            As[(kc + 3) * GBM + row] = a.w;
        }
        // Load B tile (16x64 = 256 float4), 1 per thread.
        {
            int k  = tid >> 4;
            int nc = (tid & 15) * 4;
            float4 b = *(const float4*)(B + (size_t)(k0 + k) * N + bn + nc);
            *(float4*)(Bs + k * GBN + nc) = b;
        }
        __syncthreads();

        #pragma unroll
        for (int k = 0; k < GBK; k++) {
            float ar[GTM], br[GTN];
            float4 a0 = *(const float4*)(As + k * GBM + ty * GTM);
            float4 a1 = *(const float4*)(As + k * GBM + ty * GTM + 4);
            ar[0] = a0.x; ar[1] = a0.y; ar[2] = a0.z; ar[3] = a0.w;
            ar[4] = a1.x; ar[5] = a1.y; ar[6] = a1.z; ar[7] = a1.w;
            float4 bb = *(const float4*)(Bs + k * GBN + tx * GTN);
            br[0] = bb.x; br[1] = bb.y; br[2] = bb.z; br[3] = bb.w;
            #pragma unroll
            for (int tm = 0; tm < GTM; tm++)
                #pragma unroll
                for (int tn = 0; tn < GTN; tn++)
                    acc[tm][tn] += ar[tm] * br[tn];
        }
        __syncthreads();
    }

    #pragma unroll
    for (int tm = 0; tm < GTM; tm++) {
        int gr = bm + ty * GTM + tm;
        if (gr < M) {
            #pragma unroll
            for (int tn = 0; tn < GTN; tn++) {
                int gc = bn + tx * GTN + tn;
                C[(size_t)gr * N + gc] = acc[tm][tn] + bias[gc];
            }
        }
    }
}

// ---------------- BN stats: column sums and sums of squares ------------------
__global__ void bn_stats(const float* __restrict__ x, int M, int C,
                         float* __restrict__ sums) {
    int col = threadIdx.x;          // blockDim.x == C
    float s = 0.f, s2 = 0.f;
    for (int r = blockIdx.x; r < M; r += gridDim.x) {
        float v = x[(size_t)r * C + col];
        s  += v;
        s2 += v * v;
    }
    atomicAdd(&sums[col],     s);
    atomicAdd(&sums[C + col], s2);
}

// ---------------- BN apply + ReLU (vectorized float4) ------------------------
__global__ void bn_apply(const float4* __restrict__ x, float4* __restrict__ y,
                         const float* __restrict__ sums,
                         const float* __restrict__ gamma,
                         const float* __restrict__ beta, int M, int C) {
    int idx = blockIdx.x * blockDim.x + threadIdx.x;      // float4 index
    int total = M * C / 4;
    if (idx >= total) return;
    int col = (idx * 4) % C;
    float invM = 1.0f / (float)M;
    float4 v = x[idx];
    float4 o;
    #pragma unroll
    for (int j = 0; j < 4; j++) {
        int c = col + j;
        float mean = sums[c] * invM;
        float var  = sums[C + c] * invM - mean * mean;
        float scl = gamma[c] * rsqrtf(var + BN_EPS);
        float sh  = beta[c] - mean * scl;
        float val = (&v.x)[j] * scl + sh;
        (&o.x)[j] = fmaxf(val, 0.f);
    }
    y[idx] = o;
}

// ---------------- launch ------------------------------------------------------
extern "C" void kernel_launch(void* const* d_in, const int* in_sizes, int n_in,
                              void* d_out, int out_size) {
    const float* nf  = (const float*)d_in[0];   // node_feats [10000,128]
    const float* ef  = (const float*)d_in[1];   // edge_feats [640000,128]
    const float* eps = (const float*)d_in[2];   // eps [1]
    const float* W1  = (const float*)d_in[3];   // [128,256]
    const float* b1  = (const float*)d_in[4];   // [256]
    const float* g1  = (const float*)d_in[5];   // [256]
    const float* be1 = (const float*)d_in[6];   // [256]
    const float* W2  = (const float*)d_in[7];   // [256,128]
    const float* b2  = (const float*)d_in[8];   // [128]
    const float* g2  = (const float*)d_in[9];   // [128]
    const float* be2 = (const float*)d_in[10];  // [128]
    const int*   src = (const int*)d_in[11];    // [640000]
    const int*   dst = (const int*)d_in[12];    // [640000]
    float* out = (float*)d_out;                 // [10000,128]

    float *h0, *t1, *t2, *bnsum;
    cudaGetSymbolAddress((void**)&h0,    g_h0);
    cudaGetSymbolAddress((void**)&t1,    g_t1);
    cudaGetSymbolAddress((void**)&t2,    g_t2);
    cudaGetSymbolAddress((void**)&bnsum, g_bnsum);

    zero_kernel   <<<(N_NODES + 255) / 256, 256>>>();
    hist_kernel   <<<(N_EDGES + 255) / 256, 256>>>(dst);
    scan_kernel   <<<1, 1024>>>();
    scatter_kernel<<<(N_EDGES + 255) / 256, 256>>>(dst);
    aggregate_kernel<<<(N_NODES * 32 + 255) / 256, 256>>>(nf, ef, src, eps);

    // GEMM1: h0 [10000,128] @ W1 [128,256] + b1 -> t1 [10000,256]
    {
        dim3 grid(2 * D / GBN, (N_NODES + GBM - 1) / GBM);   // (4, 79)
        sgemm_bias<<<grid, 256>>>(h0, W1, b1, t1, N_NODES, 2 * D, D);
    }
    bn_stats<<<148, 2 * D>>>(t1, N_NODES, 2 * D, bnsum);
    bn_apply<<<(N_NODES * 2 * D / 4 + 255) / 256, 256>>>((const float4*)t1,
                                                         (float4*)t1, bnsum,
                                                         g1, be1, N_NODES, 2 * D);

    // GEMM2: t1 [10000,256] @ W2 [256,128] + b2 -> t2 [10000,128]
    {
        dim3 grid(D / GBN, (N_NODES + GBM - 1) / GBM);       // (2, 79)
        sgemm_bias<<<grid, 256>>>(t1, W2, b2, t2, N_NODES, D, 2 * D);
    }
    bn_stats<<<148, D>>>(t2, N_NODES, D, bnsum + 512);
    bn_apply<<<(N_NODES * D / 4 + 255) / 256, 256>>>((const float4*)t2,
                                                     (float4*)out, bnsum + 512,
                                                     g2, be2, N_NODES, D);
}

// round 4
// speedup vs baseline: 1.1958x; 1.1958x over previous
#include <cuda_runtime.h>

#define N_NODES 10000
#define N_EDGES 640000
#define D 128
#define BN_EPS 1e-5f

// ---------------- scratch (device globals: no allocations allowed) ----------
__device__ int   g_counts [N_NODES];
__device__ int   g_cursor [N_NODES];
__device__ int   g_offsets[N_NODES + 1];
__device__ int   g_sorted [N_EDGES];
__device__ float g_h0 [N_NODES * D];        // GIN combine output        [10000,128]
__device__ float g_t1 [N_NODES * 2 * D];    // after GEMM1 (raw, pre-BN) [10000,256]
__device__ float g_t2 [N_NODES * D];        // after GEMM2 (raw, pre-BN) [10000,128]
__device__ float g_bnsum[1024];             // [0:512) stage1 sum|sumsq, [512:768) stage2 sum, [640:768) sumsq

// ---------------- zero scratch ----------------------------------------------
__global__ void zero_kernel() {
    int i = blockIdx.x * blockDim.x + threadIdx.x;
    if (i < N_NODES) g_counts[i] = 0;
    if (i < 1024)    g_bnsum[i] = 0.0f;
}

// ---------------- degree histogram ------------------------------------------
__global__ void hist_kernel(const int* __restrict__ dst) {
    int e = blockIdx.x * blockDim.x + threadIdx.x;
    if (e < N_EDGES) atomicAdd(&g_counts[dst[e]], 1);
}

// ---------------- single-block exclusive scan; cursor := offsets -------------
__global__ void scan_kernel() {
    __shared__ int s[1024];
    const int CH = (N_NODES + 1023) / 1024;   // 10
    int tid = threadIdx.x;
    int base = tid * CH;
    int sum = 0;
    for (int i = 0; i < CH; i++) {
        int idx = base + i;
        if (idx < N_NODES) sum += g_counts[idx];
    }
    s[tid] = sum;
    __syncthreads();
    for (int off = 1; off < 1024; off <<= 1) {
        int v = (tid >= off) ? s[tid - off] : 0;
        __syncthreads();
        s[tid] += v;
        __syncthreads();
    }
    int run = s[tid] - sum;   // exclusive prefix for this thread's chunk
    for (int i = 0; i < CH; i++) {
        int idx = base + i;
        if (idx < N_NODES) {
            g_offsets[idx] = run;
            g_cursor [idx] = run;           // cursor starts at offset
            run += g_counts[idx];
        }
    }
    if (tid == 1023) g_offsets[N_NODES] = s[1023];
}

// ---------------- scatter edge indices into CSR (single atomic) --------------
__global__ void scatter_kernel(const int* __restrict__ dst) {
    int e = blockIdx.x * blockDim.x + threadIdx.x;
    if (e < N_EDGES) {
        int p = atomicAdd(&g_cursor[dst[e]], 1);
        g_sorted[p] = e;
    }
}

// ---------------- per-node aggregation (one warp per node, unroll x4) --------
__global__ void aggregate_kernel(const float* __restrict__ nf,
                                 const float* __restrict__ ef,
                                 const int*   __restrict__ src,
                                 const float* __restrict__ eps) {
    int gw   = (blockIdx.x * blockDim.x + threadIdx.x) >> 5;
    int lane = threadIdx.x & 31;
    if (gw >= N_NODES) return;
    int beg = g_offsets[gw], end = g_offsets[gw + 1];

    float4 acc0 = make_float4(0.f, 0.f, 0.f, 0.f);
    float4 acc1 = make_float4(0.f, 0.f, 0.f, 0.f);
    float4 acc2 = make_float4(0.f, 0.f, 0.f, 0.f);
    float4 acc3 = make_float4(0.f, 0.f, 0.f, 0.f);

    int i = beg;
    for (; i + 4 <= end; i += 4) {
        // batch-load indices first (broadcast loads), then 8 independent row loads
        int e0 = g_sorted[i],     e1 = g_sorted[i + 1];
        int e2 = g_sorted[i + 2], e3 = g_sorted[i + 3];
        int s0 = src[e0], s1 = src[e1], s2 = src[e2], s3 = src[e3];
        float4 b0 = __ldcs((const float4*)(ef + (size_t)e0 * D) + lane);
        float4 b1 = __ldcs((const float4*)(ef + (size_t)e1 * D) + lane);
        float4 b2 = __ldcs((const float4*)(ef + (size_t)e2 * D) + lane);
        float4 b3 = __ldcs((const float4*)(ef + (size_t)e3 * D) + lane);
        float4 a0 = __ldg ((const float4*)(nf + (size_t)s0 * D) + lane);
        float4 a1 = __ldg ((const float4*)(nf + (size_t)s1 * D) + lane);
        float4 a2 = __ldg ((const float4*)(nf + (size_t)s2 * D) + lane);
        float4 a3 = __ldg ((const float4*)(nf + (size_t)s3 * D) + lane);
        acc0.x += a0.x + b0.x; acc0.y += a0.y + b0.y; acc0.z += a0.z + b0.z; acc0.w += a0.w + b0.w;
        acc1.x += a1.x + b1.x; acc1.y += a1.y + b1.y; acc1.z += a1.z + b1.z; acc1.w += a1.w + b1.w;
        acc2.x += a2.x + b2.x; acc2.y += a2.y + b2.y; acc2.z += a2.z + b2.z; acc2.w += a2.w + b2.w;
        acc3.x += a3.x + b3.x; acc3.y += a3.y + b3.y; acc3.z += a3.z + b3.z; acc3.w += a3.w + b3.w;
    }
    for (; i < end; i++) {
        int e0 = g_sorted[i];
        int s0 = src[e0];
        float4 b0 = __ldcs((const float4*)(ef + (size_t)e0 * D) + lane);
        float4 a0 = __ldg ((const float4*)(nf + (size_t)s0 * D) + lane);
        acc0.x += a0.x + b0.x; acc0.y += a0.y + b0.y;
        acc0.z += a0.z + b0.z; acc0.w += a0.w + b0.w;
    }
    float cnt = (float)(end - beg);
    float inv = 1.0f / fmaxf(cnt, 1.0f);
    float sc  = 1.0f + eps[0];
    float4 m  = ((const float4*)(nf + (size_t)gw * D))[lane];
    float4 o;
    o.x = sc * m.x + (acc0.x + acc1.x + acc2.x + acc3.x) * inv;
    o.y = sc * m.y + (acc0.y + acc1.y + acc2.y + acc3.y) * inv;
    o.z = sc * m.z + (acc0.z + acc1.z + acc2.z + acc3.z) * inv;
    o.w = sc * m.w + (acc0.w + acc1.w + acc2.w + acc3.w) * inv;
    ((float4*)(g_h0 + (size_t)gw * D))[lane] = o;
}

// ---------------- fused SGEMM ------------------------------------------------
// C[M,N] = f(A)[M,K] @ B[K,N] + bias, where f = identity or BN1+ReLU (per-K-col)
// Epilogue: per-column sum & sumsq of C accumulated into bn_out (BN stats).
#define GBM 128
#define GBN 64
#define GBK 16
#define GTM 8
#define GTN 4

template <bool BN_IN>
__global__ __launch_bounds__(256) void sgemm_fused(
    const float* __restrict__ A, const float* __restrict__ B,
    const float* __restrict__ bias, float* __restrict__ C,
    int M, int N, int K,
    const float* __restrict__ bn_sums,   // stats of A's pre-BN values [K | K]
    const float* __restrict__ bn_gamma,
    const float* __restrict__ bn_beta,
    float* __restrict__ bn_out)          // [N | N] sums / sumsq
{
    __shared__ float As[GBK * GBM];      // 8 KB (reused for stats reduction)
    __shared__ float Bs[GBK * GBN];      // 4 KB
    __shared__ float s_scl[256];
    __shared__ float s_sh [256];

    int tid = threadIdx.x;
    int tx = tid & 15;      // N direction (16)
    int ty = tid >> 4;      // M direction (16)
    int bm = blockIdx.y * GBM;
    int bn = blockIdx.x * GBN;

    if (BN_IN) {
        float invM = 1.0f / (float)M;
        for (int c = tid; c < K; c += 256) {
            float mean = bn_sums[c] * invM;
            float var  = bn_sums[K + c] * invM - mean * mean;
            float scl  = bn_gamma[c] * rsqrtf(var + BN_EPS);
            s_scl[c] = scl;
            s_sh [c] = bn_beta[c] - mean * scl;
        }
        __syncthreads();
    }

    float acc[GTM][GTN];
    #pragma unroll
    for (int a = 0; a < GTM; a++)
        #pragma unroll
        for (int b = 0; b < GTN; b++) acc[a][b] = 0.f;

    for (int k0 = 0; k0 < K; k0 += GBK) {
        // Load A tile (128x16 = 512 float4), 2 per thread; store transposed.
        #pragma unroll
        for (int t = 0; t < 2; t++) {
            int j   = tid + t * 256;
            int row = j >> 2;
            int kc  = (j & 3) * 4;
            int gr  = bm + row;
            float4 a = make_float4(0.f, 0.f, 0.f, 0.f);
            if (gr < M) {
                a = *(const float4*)(A + (size_t)gr * K + k0 + kc);
                if (BN_IN) {
                    a.x = fmaxf(fmaf(a.x, s_scl[k0 + kc + 0], s_sh[k0 + kc + 0]), 0.f);
                    a.y = fmaxf(fmaf(a.y, s_scl[k0 + kc + 1], s_sh[k0 + kc + 1]), 0.f);
                    a.z = fmaxf(fmaf(a.z, s_scl[k0 + kc + 2], s_sh[k0 + kc + 2]), 0.f);
                    a.w = fmaxf(fmaf(a.w, s_scl[k0 + kc + 3], s_sh[k0 + kc + 3]), 0.f);
                }
            }
            As[(kc + 0) * GBM + row] = a.x;
            As[(kc + 1) * GBM + row] = a.y;
            As[(kc + 2) * GBM + row] = a.z;
            As[(kc + 3) * GBM + row] = a.w;
        }
        // Load B tile (16x64 = 256 float4), 1 per thread.
        {
            int k  = tid >> 4;
            int nc = (tid & 15) * 4;
            float4 b = *(const float4*)(B + (size_t)(k0 + k) * N + bn + nc);
            *(float4*)(Bs + k * GBN + nc) = b;
        }
        __syncthreads();

        #pragma unroll
        for (int k = 0; k < GBK; k++) {
            float ar[GTM], br[GTN];
            float4 a0 = *(const float4*)(As + k * GBM + ty * GTM);
            float4 a1 = *(const float4*)(As + k * GBM + ty * GTM + 4);
            ar[0] = a0.x; ar[1] = a0.y; ar[2] = a0.z; ar[3] = a0.w;
            ar[4] = a1.x; ar[5] = a1.y; ar[6] = a1.z; ar[7] = a1.w;
            float4 bb = *(const float4*)(Bs + k * GBN + tx * GTN);
            br[0] = bb.x; br[1] = bb.y; br[2] = bb.z; br[3] = bb.w;
            #pragma unroll
            for (int tm = 0; tm < GTM; tm++)
                #pragma unroll
                for (int tn = 0; tn < GTN; tn++)
                    acc[tm][tn] += ar[tm] * br[tn];
        }
        __syncthreads();
    }

    // epilogue: bias add, store, and per-column partial BN stats
    float cs [GTN] = {0.f, 0.f, 0.f, 0.f};
    float cs2[GTN] = {0.f, 0.f, 0.f, 0.f};
    #pragma unroll
    for (int tm = 0; tm < GTM; tm++) {
        int gr = bm + ty * GTM + tm;
        if (gr < M) {
            #pragma unroll
            for (int tn = 0; tn < GTN; tn++) {
                int gc = bn + tx * GTN + tn;
                float v = acc[tm][tn] + bias[gc];
                C[(size_t)gr * N + gc] = v;
                cs [tn] += v;
                cs2[tn] += v * v;
            }
        }
    }
    // reduce across the 16 ty-groups via shared memory (reuse As: 2048 floats)
    float* red = As;
    #pragma unroll
    for (int tn = 0; tn < GTN; tn++) {
        red[ty * GBN + tx * GTN + tn]        = cs [tn];
        red[1024 + ty * GBN + tx * GTN + tn] = cs2[tn];
    }
    __syncthreads();
    if (tid < GBN) {
        float s = 0.f, s2 = 0.f;
        #pragma unroll
        for (int t = 0; t < 16; t++) {
            s  += red[t * GBN + tid];
            s2 += red[1024 + t * GBN + tid];
        }
        atomicAdd(&bn_out[bn + tid],     s);
        atomicAdd(&bn_out[N + bn + tid], s2);
    }
}

// ---------------- BN apply + ReLU (vectorized float4) ------------------------
__global__ void bn_apply(const float4* __restrict__ x, float4* __restrict__ y,
                         const float* __restrict__ sums,
                         const float* __restrict__ gamma,
                         const float* __restrict__ beta, int M, int C) {
    int idx = blockIdx.x * blockDim.x + threadIdx.x;      // float4 index
    int total = M * C / 4;
    if (idx >= total) return;
    int col = (idx * 4) % C;
    float invM = 1.0f / (float)M;
    float4 v = x[idx];
    float4 o;
    #pragma unroll
    for (int j = 0; j < 4; j++) {
        int c = col + j;
        float mean = sums[c] * invM;
        float var  = sums[C + c] * invM - mean * mean;
        float scl = gamma[c] * rsqrtf(var + BN_EPS);
        float sh  = beta[c] - mean * scl;
        float val = (&v.x)[j] * scl + sh;
        (&o.x)[j] = fmaxf(val, 0.f);
    }
    y[idx] = o;
}

// ---------------- launch ------------------------------------------------------
extern "C" void kernel_launch(void* const* d_in, const int* in_sizes, int n_in,
                              void* d_out, int out_size) {
    const float* nf  = (const float*)d_in[0];   // node_feats [10000,128]
    const float* ef  = (const float*)d_in[1];   // edge_feats [640000,128]
    const float* eps = (const float*)d_in[2];   // eps [1]
    const float* W1  = (const float*)d_in[3];   // [128,256]
    const float* b1  = (const float*)d_in[4];   // [256]
    const float* g1  = (const float*)d_in[5];   // [256]
    const float* be1 = (const float*)d_in[6];   // [256]
    const float* W2  = (const float*)d_in[7];   // [256,128]
    const float* b2  = (const float*)d_in[8];   // [128]
    const float* g2  = (const float*)d_in[9];   // [128]
    const float* be2 = (const float*)d_in[10];  // [128]
    const int*   src = (const int*)d_in[11];    // [640000]
    const int*   dst = (const int*)d_in[12];    // [640000]
    float* out = (float*)d_out;                 // [10000,128]

    float *h0, *t1, *t2, *bnsum;
    cudaGetSymbolAddress((void**)&h0,    g_h0);
    cudaGetSymbolAddress((void**)&t1,    g_t1);
    cudaGetSymbolAddress((void**)&t2,    g_t2);
    cudaGetSymbolAddress((void**)&bnsum, g_bnsum);

    zero_kernel   <<<(N_NODES + 255) / 256, 256>>>();
    hist_kernel   <<<(N_EDGES + 255) / 256, 256>>>(dst);
    scan_kernel   <<<1, 1024>>>();
    scatter_kernel<<<(N_EDGES + 255) / 256, 256>>>(dst);
    aggregate_kernel<<<(N_NODES * 32 + 255) / 256, 256>>>(nf, ef, src, eps);

    // GEMM1: h0 @ W1 + b1 -> t1 (raw); epilogue accumulates BN1 stats
    {
        dim3 grid(2 * D / GBN, (N_NODES + GBM - 1) / GBM);   // (4, 79)
        sgemm_fused<false><<<grid, 256>>>(h0, W1, b1, t1, N_NODES, 2 * D, D,
                                          nullptr, nullptr, nullptr, bnsum);
    }
    // GEMM2: relu(BN1(t1)) @ W2 + b2 -> t2 (raw); epilogue accumulates BN2 stats
    {
        dim3 grid(D / GBN, (N_NODES + GBM - 1) / GBM);       // (2, 79)
        sgemm_fused<true><<<grid, 256>>>(t1, W2, b2, t2, N_NODES, D, 2 * D,
                                         bnsum, g1, be1, bnsum + 512);
    }
    // BN2 apply + ReLU -> out
    bn_apply<<<(N_NODES * D / 4 + 255) / 256, 256>>>((const float4*)t2,
                                                     (float4*)out, bnsum + 512,
                                                     g2, be2, N_NODES, D);
}